// round 6
// baseline (speedup 1.0000x reference)
#include <cuda_runtime.h>
#include <cstdint>

// scatter_mean via counting-sort + gather:
//   k0: zero counters
//   k1: histogram of index
//   k2: exclusive scan -> offsets (+ cursor copy)
//   k3: bucket row ids into segment-sorted order
//   k4: per-segment gather-reduce (one warp per segment), divide, store
//
// x: [N, 64] f32, index: [N] int32, out: [S, 64] f32  (N=4194304, S=100000)

#define S_MAX 100000
#define N_MAX 4194304

__device__ int g_cnt[S_MAX];
__device__ int g_off[S_MAX];
__device__ int g_cur[S_MAX];
__device__ int g_rowid[N_MAX];

__global__ void zero_kernel(int S) {
    int i = blockIdx.x * blockDim.x + threadIdx.x;
    if (i < S) g_cnt[i] = 0;
}

__global__ void hist_kernel(const int4* __restrict__ idx4, int nquads) {
    int i = blockIdx.x * blockDim.x + threadIdx.x;
    if (i >= nquads) return;
    int4 v = idx4[i];
    atomicAdd(&g_cnt[v.x], 1);
    atomicAdd(&g_cnt[v.y], 1);
    atomicAdd(&g_cnt[v.z], 1);
    atomicAdd(&g_cnt[v.w], 1);
}

// Single-block exclusive scan over S counts (chunks of 1024).
__global__ void scan_kernel(int S) {
    __shared__ int warp_sums[32];
    __shared__ int s_running;
    int tid = threadIdx.x;
    int lane = tid & 31;
    int wid = tid >> 5;
    if (tid == 0) s_running = 0;
    __syncthreads();

    for (int base = 0; base < S; base += 1024) {
        int i = base + tid;
        int c = (i < S) ? g_cnt[i] : 0;

        // warp inclusive scan
        int v = c;
        #pragma unroll
        for (int d = 1; d < 32; d <<= 1) {
            int n = __shfl_up_sync(0xFFFFFFFFu, v, d);
            if (lane >= d) v += n;
        }
        if (lane == 31) warp_sums[wid] = v;
        __syncthreads();

        // scan warp sums (warp 0)
        if (wid == 0) {
            int w = warp_sums[lane];
            #pragma unroll
            for (int d = 1; d < 32; d <<= 1) {
                int n = __shfl_up_sync(0xFFFFFFFFu, w, d);
                if (lane >= d) w += n;
            }
            warp_sums[lane] = w;
        }
        __syncthreads();

        int warp_off = (wid == 0) ? 0 : warp_sums[wid - 1];
        int running = s_running;
        int excl = running + warp_off + v - c;
        if (i < S) {
            g_off[i] = excl;
            g_cur[i] = excl;
        }
        __syncthreads();                       // all reads of s_running/warp_sums done
        if (tid == 0) s_running = running + warp_sums[31];
        __syncthreads();                       // update visible before next chunk
    }
}

__global__ void bucket_kernel(const int4* __restrict__ idx4, int nquads) {
    int i = blockIdx.x * blockDim.x + threadIdx.x;
    if (i >= nquads) return;
    int4 v = idx4[i];
    int r = i * 4;
    int p0 = atomicAdd(&g_cur[v.x], 1); g_rowid[p0] = r + 0;
    int p1 = atomicAdd(&g_cur[v.y], 1); g_rowid[p1] = r + 1;
    int p2 = atomicAdd(&g_cur[v.z], 1); g_rowid[p2] = r + 2;
    int p3 = atomicAdd(&g_cur[v.w], 1); g_rowid[p3] = r + 3;
}

// One warp per segment: sum rows, divide by count, store 64 floats.
__global__ void reduce_kernel(const float2* __restrict__ x2,
                              float2* __restrict__ out2,
                              int S) {
    int gw = (blockIdx.x * blockDim.x + threadIdx.x) >> 5;
    int lane = threadIdx.x & 31;
    if (gw >= S) return;

    int start = g_off[gw];
    int cnt   = g_cnt[gw];

    float2 a0 = {0.f, 0.f}, a1 = {0.f, 0.f}, a2 = {0.f, 0.f}, a3 = {0.f, 0.f};
    int i = 0;
    for (; i + 4 <= cnt; i += 4) {
        int r0 = g_rowid[start + i + 0];
        int r1 = g_rowid[start + i + 1];
        int r2 = g_rowid[start + i + 2];
        int r3 = g_rowid[start + i + 3];
        float2 v0 = x2[(long long)r0 * 32 + lane];
        float2 v1 = x2[(long long)r1 * 32 + lane];
        float2 v2 = x2[(long long)r2 * 32 + lane];
        float2 v3 = x2[(long long)r3 * 32 + lane];
        a0.x += v0.x; a0.y += v0.y;
        a1.x += v1.x; a1.y += v1.y;
        a2.x += v2.x; a2.y += v2.y;
        a3.x += v3.x; a3.y += v3.y;
    }
    for (; i < cnt; i++) {
        int r = g_rowid[start + i];
        float2 v = x2[(long long)r * 32 + lane];
        a0.x += v.x; a0.y += v.y;
    }

    float sx = a0.x + a1.x + a2.x + a3.x;
    float sy = a0.y + a1.y + a2.y + a3.y;
    float inv = 1.0f / (float)max(cnt, 1);

    float2 o; o.x = sx * inv; o.y = sy * inv;
    out2[(long long)gw * 32 + lane] = o;
}

extern "C" void kernel_launch(void* const* d_in, const int* in_sizes, int n_in,
                              void* d_out, int out_size) {
    const float2* x2   = (const float2*)d_in[0];
    const int4*   idx4 = (const int4*)d_in[1];
    float2*       out2 = (float2*)d_out;

    int nrows = in_sizes[1];        // 4194304
    int S     = out_size / 64;      // 100000
    int nquads = nrows / 4;

    {
        int threads = 256;
        zero_kernel<<<(S + threads - 1) / threads, threads>>>(S);
    }
    {
        int threads = 256;
        hist_kernel<<<(nquads + threads - 1) / threads, threads>>>(idx4, nquads);
    }
    scan_kernel<<<1, 1024>>>(S);
    {
        int threads = 256;
        bucket_kernel<<<(nquads + threads - 1) / threads, threads>>>(idx4, nquads);
    }
    {
        int threads = 256;                    // 8 warps per block
        int warps_needed = S;
        int blocks = (warps_needed * 32 + threads - 1) / threads;
        reduce_kernel<<<blocks, threads>>>(x2, out2, S);
    }
}

// round 7
// speedup vs baseline: 1.6549x; 1.6549x over previous
#include <cuda_runtime.h>
#include <cstdint>

// scatter_mean: out[s, :] = mean over rows r with index[r]==s of x[r, :]
// x: [N, 64] f32, index: [N] int32, out: [S, 64] f32  (N=4194304, S=100000)
//
// Atomic-scatter route (measured at the LTS cap):
//   k1: zero out + counts (float4 stores)
//   k2: thread-per-float4 scatter with red.global.add.v4.f32, __ldcs on x
//   k3: divide by max(count,1), float4

#define DVEC 16          // 64 floats = 16 float4 per row
#define MAX_SEG 100000

__device__ float g_counts[MAX_SEG];

__global__ void init_kernel(float4* __restrict__ out4, int nquads_out, int S) {
    int i = blockIdx.x * blockDim.x + threadIdx.x;
    const float4 z = {0.f, 0.f, 0.f, 0.f};
    if (i < nquads_out) out4[i] = z;
    // counts live at the tail of the same index space
    int c = i - nquads_out;
    if (c >= 0 && c < S) g_counts[c] = 0.0f;
}

__global__ void scatter_kernel(const float4* __restrict__ x,
                               const int* __restrict__ idx,
                               float* __restrict__ out,
                               int nrows) {
    long long t = (long long)blockIdx.x * blockDim.x + threadIdx.x;
    long long total = (long long)nrows * DVEC;
    if (t >= total) return;

    int row = (int)(t >> 4);
    int q   = (int)(t & 15);

    int s = __ldg(idx + row);        // broadcast across 16 lanes -> 1 sector
    float4 v = __ldcs(x + t);        // streaming, evict-first: protect L2 for out

    float* dst = out + (long long)s * 64 + q * 4;
    asm volatile("red.global.add.v4.f32 [%0], {%1, %2, %3, %4};"
                 :: "l"(dst), "f"(v.x), "f"(v.y), "f"(v.z), "f"(v.w)
                 : "memory");

    if (q == 0) atomicAdd(&g_counts[s], 1.0f);
}

__global__ void divide_kernel(float4* __restrict__ out4, int nquads_out) {
    int i = blockIdx.x * blockDim.x + threadIdx.x;
    if (i >= nquads_out) return;
    int s = i >> 4;                  // 16 float4 per segment
    float c = g_counts[s];
    float inv = 1.0f / fmaxf(c, 1.0f);
    float4 v = out4[i];
    v.x *= inv; v.y *= inv; v.z *= inv; v.w *= inv;
    out4[i] = v;
}

extern "C" void kernel_launch(void* const* d_in, const int* in_sizes, int n_in,
                              void* d_out, int out_size) {
    const float4* x   = (const float4*)d_in[0];
    const int*    idx = (const int*)d_in[1];
    float*        out = (float*)d_out;
    float4*       out4 = (float4*)d_out;

    int nrows = in_sizes[1];              // N = 4194304
    int S     = out_size / 64;            // 100000
    int nquads_out = out_size / 4;        // S * 16

    {
        int threads = 256;
        int work = nquads_out + S;
        int blocks = (work + threads - 1) / threads;
        init_kernel<<<blocks, threads>>>(out4, nquads_out, S);
    }
    {
        long long total = (long long)nrows * DVEC;   // 67,108,864 threads
        int threads = 256;
        long long blocks = (total + threads - 1) / threads;
        scatter_kernel<<<(unsigned int)blocks, threads>>>(x, idx, out, nrows);
    }
    {
        int threads = 256;
        int blocks = (nquads_out + threads - 1) / threads;
        divide_kernel<<<blocks, threads>>>(out4, nquads_out);
    }
}

// round 8
// speedup vs baseline: 1.6719x; 1.0103x over previous
#include <cuda_runtime.h>
#include <cstdint>

// scatter_mean via counting-sort + gather (v2):
//   k0: zero counters
//   k1: histogram of index (int4 loads)
//   k2a/k2b/k2c: 3-phase multi-block exclusive scan -> g_off, g_cur
//   k3: bucket row ids (8 rows/thread, independent atomic chains)
//   k4: per-segment gather-reduce, 8 rows in flight, fused divide, direct store
//
// x: [N, 64] f32, index: [N] int32, out: [S, 64] f32  (N=4194304, S=100000)

#define S_MAX 100000
#define N_MAX 4194304
#define SCAN_BLK 1024
#define NB_MAX 128            // ceil(100000/1024)=98 block sums

__device__ int g_cnt[S_MAX];
__device__ int g_off[S_MAX];
__device__ int g_cur[S_MAX];
__device__ int g_bsum[NB_MAX];
__device__ int g_rowid[N_MAX];

__global__ void zero_kernel(int S) {
    int i = blockIdx.x * blockDim.x + threadIdx.x;
    if (i < S) g_cnt[i] = 0;
}

__global__ void hist_kernel(const int4* __restrict__ idx4, int nquads) {
    int i = blockIdx.x * blockDim.x + threadIdx.x;
    if (i >= nquads) return;
    int4 v = idx4[i];
    atomicAdd(&g_cnt[v.x], 1);
    atomicAdd(&g_cnt[v.y], 1);
    atomicAdd(&g_cnt[v.z], 1);
    atomicAdd(&g_cnt[v.w], 1);
}

// Phase A: per-block exclusive scan of 1024 counts; block total -> g_bsum.
__global__ void scanA_kernel(int S) {
    __shared__ int warp_sums[32];
    int tid = threadIdx.x;
    int lane = tid & 31;
    int wid = tid >> 5;
    int i = blockIdx.x * SCAN_BLK + tid;
    int c = (i < S) ? g_cnt[i] : 0;

    int v = c;
    #pragma unroll
    for (int d = 1; d < 32; d <<= 1) {
        int n = __shfl_up_sync(0xFFFFFFFFu, v, d);
        if (lane >= d) v += n;
    }
    if (lane == 31) warp_sums[wid] = v;
    __syncthreads();
    if (wid == 0) {
        int w = warp_sums[lane];
        #pragma unroll
        for (int d = 1; d < 32; d <<= 1) {
            int n = __shfl_up_sync(0xFFFFFFFFu, w, d);
            if (lane >= d) w += n;
        }
        warp_sums[lane] = w;
    }
    __syncthreads();

    int warp_off = (wid == 0) ? 0 : warp_sums[wid - 1];
    if (i < S) g_off[i] = warp_off + v - c;       // exclusive within block
    if (tid == 0) g_bsum[blockIdx.x] = warp_sums[31];
}

// Phase B: single block, exclusive scan of NB block sums in place.
__global__ void scanB_kernel(int NB) {
    __shared__ int sm[NB_MAX];
    int tid = threadIdx.x;
    int c = (tid < NB) ? g_bsum[tid] : 0;
    sm[tid] = c;
    __syncthreads();
    #pragma unroll
    for (int d = 1; d < NB_MAX; d <<= 1) {
        int t = (tid >= d) ? sm[tid - d] : 0;
        __syncthreads();
        sm[tid] += t;
        __syncthreads();
    }
    if (tid < NB) g_bsum[tid] = sm[tid] - c;      // exclusive
}

// Phase C: add block offsets, seed cursors.
__global__ void scanC_kernel(int S) {
    int i = blockIdx.x * SCAN_BLK + threadIdx.x;
    if (i >= S) return;
    int o = g_off[i] + g_bsum[blockIdx.x];
    g_off[i] = o;
    g_cur[i] = o;
}

// 8 rows per thread: 8 independent atomicAdd->STG chains for MLP.
__global__ void bucket_kernel(const int4* __restrict__ idx4, int nquads) {
    int i = (blockIdx.x * blockDim.x + threadIdx.x) * 2;
    if (i >= nquads) return;
    int4 a = idx4[i];
    int4 b = (i + 1 < nquads) ? idx4[i + 1] : make_int4(0, 0, 0, 0);
    int r = i * 4;
    int p0 = atomicAdd(&g_cur[a.x], 1);
    int p1 = atomicAdd(&g_cur[a.y], 1);
    int p2 = atomicAdd(&g_cur[a.z], 1);
    int p3 = atomicAdd(&g_cur[a.w], 1);
    g_rowid[p0] = r + 0;
    g_rowid[p1] = r + 1;
    g_rowid[p2] = r + 2;
    g_rowid[p3] = r + 3;
    if (i + 1 < nquads) {
        int p4 = atomicAdd(&g_cur[b.x], 1);
        int p5 = atomicAdd(&g_cur[b.y], 1);
        int p6 = atomicAdd(&g_cur[b.z], 1);
        int p7 = atomicAdd(&g_cur[b.w], 1);
        g_rowid[p4] = r + 4;
        g_rowid[p5] = r + 5;
        g_rowid[p6] = r + 6;
        g_rowid[p7] = r + 7;
    }
}

// One warp per segment, 8 rows in flight, fused divide + direct store.
__global__ void reduce_kernel(const float2* __restrict__ x2,
                              float2* __restrict__ out2,
                              int S) {
    int gw = (blockIdx.x * blockDim.x + threadIdx.x) >> 5;
    int lane = threadIdx.x & 31;
    if (gw >= S) return;

    int start = g_off[gw];
    int cnt   = g_cnt[gw];

    float2 acc0 = {0.f, 0.f}, acc1 = {0.f, 0.f};
    int i = 0;
    for (; i + 8 <= cnt; i += 8) {
        int r0 = g_rowid[start + i + 0];
        int r1 = g_rowid[start + i + 1];
        int r2 = g_rowid[start + i + 2];
        int r3 = g_rowid[start + i + 3];
        int r4 = g_rowid[start + i + 4];
        int r5 = g_rowid[start + i + 5];
        int r6 = g_rowid[start + i + 6];
        int r7 = g_rowid[start + i + 7];
        float2 v0 = __ldcs(x2 + (long long)r0 * 32 + lane);
        float2 v1 = __ldcs(x2 + (long long)r1 * 32 + lane);
        float2 v2 = __ldcs(x2 + (long long)r2 * 32 + lane);
        float2 v3 = __ldcs(x2 + (long long)r3 * 32 + lane);
        float2 v4 = __ldcs(x2 + (long long)r4 * 32 + lane);
        float2 v5 = __ldcs(x2 + (long long)r5 * 32 + lane);
        float2 v6 = __ldcs(x2 + (long long)r6 * 32 + lane);
        float2 v7 = __ldcs(x2 + (long long)r7 * 32 + lane);
        acc0.x += v0.x + v2.x + v4.x + v6.x;
        acc0.y += v0.y + v2.y + v4.y + v6.y;
        acc1.x += v1.x + v3.x + v5.x + v7.x;
        acc1.y += v1.y + v3.y + v5.y + v7.y;
    }
    for (; i < cnt; i++) {
        int r = g_rowid[start + i];
        float2 v = __ldcs(x2 + (long long)r * 32 + lane);
        acc0.x += v.x; acc0.y += v.y;
    }

    float inv = 1.0f / (float)max(cnt, 1);
    float2 o;
    o.x = (acc0.x + acc1.x) * inv;
    o.y = (acc0.y + acc1.y) * inv;
    out2[(long long)gw * 32 + lane] = o;
}

extern "C" void kernel_launch(void* const* d_in, const int* in_sizes, int n_in,
                              void* d_out, int out_size) {
    const float2* x2   = (const float2*)d_in[0];
    const int4*   idx4 = (const int4*)d_in[1];
    float2*       out2 = (float2*)d_out;

    int nrows  = in_sizes[1];        // 4194304
    int S      = out_size / 64;      // 100000
    int nquads = nrows / 4;          // 1048576
    int NB     = (S + SCAN_BLK - 1) / SCAN_BLK;   // 98

    {
        int threads = 256;
        zero_kernel<<<(S + threads - 1) / threads, threads>>>(S);
    }
    {
        int threads = 256;
        hist_kernel<<<(nquads + threads - 1) / threads, threads>>>(idx4, nquads);
    }
    scanA_kernel<<<NB, SCAN_BLK>>>(S);
    scanB_kernel<<<1, NB_MAX>>>(NB);
    scanC_kernel<<<NB, SCAN_BLK>>>(S);
    {
        int threads = 256;
        int nthreads_needed = (nquads + 1) / 2;
        bucket_kernel<<<(nthreads_needed + threads - 1) / threads, threads>>>(idx4, nquads);
    }
    {
        int threads = 256;                           // 8 warps/block
        int blocks = (S * 32 + threads - 1) / threads;
        reduce_kernel<<<blocks, threads>>>(x2, out2, S);
    }
}